// round 2
// baseline (speedup 1.0000x reference)
#include <cuda_runtime.h>

#define NN 100000
#define EE 1600000
#define DD 128
#define NEXP 8
#define SCAN_NBLK 98            // ceil(NN/1024)
#define EPSV 1e-5f
#define GEMM_SMEM 196608        // (32768 + 16384) floats * 4B

// ---------------- scratch (static device globals; no allocations) ----------------
__device__ int   g_deg[NN];
__device__ int   g_off[NN];
__device__ int   g_cur[NN];
__device__ float g_inv_deg[NN];
__device__ int   g_srcs[EE];
__device__ int   g_bsum[SCAN_NBLK];
__device__ int   g_is64;
__device__ float g_agg0[NN * DD];
__device__ float g_agg1[NN * DD];
__device__ float g_h[NN * DD];
__device__ float g_stats[2 * DD];
__device__ float g_out_tmp[(size_t)NEXP * NN * DD];   // [8][N][128], ~410MB

// ---------------- small utility kernels ----------------
__global__ void k_detect(const int* __restrict__ ei32) {
    if (threadIdx.x == 0) {
        int hi_zero = 1;
        for (int i = 0; i < 64; i++)
            if (ei32[2 * i + 1] != 0) { hi_zero = 0; break; }
        g_is64 = hi_zero;
    }
}

__global__ void k_zero_deg() {
    int i = blockIdx.x * blockDim.x + threadIdx.x;
    if (i < NN) g_deg[i] = 0;
}

__global__ void k_zero_stats() {
    int i = threadIdx.x;
    if (i < 2 * DD) g_stats[i] = 0.0f;
}

__global__ void k_count(const int* __restrict__ ei32) {
    int i = blockIdx.x * blockDim.x + threadIdx.x;
    if (i < EE) {
        int d = g_is64 ? ei32[2 * (EE + i)] : ei32[EE + i];
        if ((unsigned)d < NN) atomicAdd(&g_deg[d], 1);
    }
}

// block-wise exclusive scan (Hillis-Steele inclusive, then subtract own)
__global__ void k_scan1() {
    __shared__ int s[1024];
    int t = threadIdx.x;
    int i = blockIdx.x * 1024 + t;
    int v = (i < NN) ? g_deg[i] : 0;
    s[t] = v;
    __syncthreads();
    for (int d = 1; d < 1024; d <<= 1) {
        int add = (t >= d) ? s[t - d] : 0;
        __syncthreads();
        s[t] += add;
        __syncthreads();
    }
    if (i < NN) g_off[i] = s[t] - v;
    if (t == 1023) g_bsum[blockIdx.x] = s[1023];
}

__global__ void k_scan2() {
    if (threadIdx.x == 0) {
        int run = 0;
        for (int i = 0; i < SCAN_NBLK; i++) {
            int v = g_bsum[i];
            g_bsum[i] = run;
            run += v;
        }
    }
}

__global__ void k_scan3() {
    int i = blockIdx.x * blockDim.x + threadIdx.x;
    if (i >= NN) return;
    int off = g_off[i] + g_bsum[i >> 10];
    g_off[i] = off;
    g_cur[i] = off;
    int dg = g_deg[i];
    g_inv_deg[i] = 1.0f / (float)(dg > 0 ? dg : 1);
}

__global__ void k_fill(const int* __restrict__ ei32) {
    int i = blockIdx.x * blockDim.x + threadIdx.x;
    if (i < EE) {
        int is64 = g_is64;
        int d = is64 ? ei32[2 * (EE + i)] : ei32[EE + i];
        int s = is64 ? ei32[2 * i]        : ei32[i];
        if ((unsigned)d < NN && (unsigned)s < NN) {
            int pos = atomicAdd(&g_cur[d], 1);
            g_srcs[pos] = s;
        }
    }
}

// ---------------- mean aggregation: out[n] = inv_deg[n] * sum_{e: dst=n} feat[src[e]] ----------------
// one warp per node, each lane owns 4 floats (float4)
__global__ void k_aggregate(const float* __restrict__ feat, float* __restrict__ out) {
    int gw = (blockIdx.x * blockDim.x + threadIdx.x) >> 5;
    int lane = threadIdx.x & 31;
    if (gw >= NN) return;
    int start = g_off[gw];
    int cnt   = g_cur[gw] - start;   // actual filled count (== deg when indices valid)
    const float4* f4 = (const float4*)feat;
    float4 acc = make_float4(0.f, 0.f, 0.f, 0.f);
    int j = 0;
    for (; j + 4 <= cnt; j += 4) {
        int s0 = g_srcs[start + j + 0];
        int s1 = g_srcs[start + j + 1];
        int s2 = g_srcs[start + j + 2];
        int s3 = g_srcs[start + j + 3];
        float4 v0 = f4[s0 * 32 + lane];
        float4 v1 = f4[s1 * 32 + lane];
        float4 v2 = f4[s2 * 32 + lane];
        float4 v3 = f4[s3 * 32 + lane];
        acc.x += (v0.x + v1.x) + (v2.x + v3.x);
        acc.y += (v0.y + v1.y) + (v2.y + v3.y);
        acc.z += (v0.z + v1.z) + (v2.z + v3.z);
        acc.w += (v0.w + v1.w) + (v2.w + v3.w);
    }
    for (; j < cnt; j++) {
        int s = g_srcs[start + j];
        float4 v = f4[s * 32 + lane];
        acc.x += v.x; acc.y += v.y; acc.z += v.z; acc.w += v.w;
    }
    float sc = g_inv_deg[gw];
    ((float4*)out)[gw * 32 + lane] =
        make_float4(acc.x * sc, acc.y * sc, acc.z * sc, acc.w * sc);
}

// ---------------- fused dual GEMM: C = A@W1 + B@W2 + bias ; optional column stats ----------------
// tile: 64 nodes x 128 cols, 256 threads, each thread 8 nodes x 4 cols
__global__ void __launch_bounds__(256)
k_gemm(const float* __restrict__ A, const float* __restrict__ Bf,
       const float* __restrict__ W1, const float* __restrict__ W2,
       const float* __restrict__ bias, float* __restrict__ Cout,
       int do_stats)
{
    extern __shared__ float sm[];
    float* Ws = sm;              // [256][128]
    float* As = sm + 32768;      // [64][256]
    int tid = threadIdx.x;
    int tx = tid & 31;           // col group: cols 4*tx .. 4*tx+3
    int ty = tid >> 5;           // node group: nodes ty*8 .. ty*8+7
    int n0 = blockIdx.x * 64;

    // load weights into smem: rows 0..127 = W1, 128..255 = W2
    float4* Wsf4 = (float4*)Ws;
    const float4* W1f4 = (const float4*)W1;
    const float4* W2f4 = (const float4*)W2;
    for (int i = tid; i < 4096; i += 256) Wsf4[i] = W1f4[i];
    for (int i = tid; i < 4096; i += 256) Wsf4[4096 + i] = W2f4[i];

    // load A-tile: As[node][0..127] = A[n], As[node][128..255] = Bf[n]
    float4* Asf4 = (float4*)As;
    const float4* Af4 = (const float4*)A;
    const float4* Bff4 = (const float4*)Bf;
    for (int i = tid; i < 4096; i += 256) {
        int node = i >> 6;
        int kk = i & 63;
        int n = n0 + node;
        float4 v = make_float4(0.f, 0.f, 0.f, 0.f);
        if (n < NN) v = (kk < 32) ? Af4[n * 32 + kk] : Bff4[n * 32 + (kk - 32)];
        Asf4[i] = v;
    }
    __syncthreads();

    float4 acc[8];
#pragma unroll
    for (int i = 0; i < 8; i++) acc[i] = make_float4(0.f, 0.f, 0.f, 0.f);

    for (int k4 = 0; k4 < 64; k4++) {
        float4 w0 = Wsf4[(k4 * 4 + 0) * 32 + tx];
        float4 w1 = Wsf4[(k4 * 4 + 1) * 32 + tx];
        float4 w2 = Wsf4[(k4 * 4 + 2) * 32 + tx];
        float4 w3 = Wsf4[(k4 * 4 + 3) * 32 + tx];
#pragma unroll
        for (int i = 0; i < 8; i++) {
            float4 a = Asf4[(ty * 8 + i) * 64 + k4];
            acc[i].x = fmaf(a.x, w0.x, acc[i].x);
            acc[i].y = fmaf(a.x, w0.y, acc[i].y);
            acc[i].z = fmaf(a.x, w0.z, acc[i].z);
            acc[i].w = fmaf(a.x, w0.w, acc[i].w);
            acc[i].x = fmaf(a.y, w1.x, acc[i].x);
            acc[i].y = fmaf(a.y, w1.y, acc[i].y);
            acc[i].z = fmaf(a.y, w1.z, acc[i].z);
            acc[i].w = fmaf(a.y, w1.w, acc[i].w);
            acc[i].x = fmaf(a.z, w2.x, acc[i].x);
            acc[i].y = fmaf(a.z, w2.y, acc[i].y);
            acc[i].z = fmaf(a.z, w2.z, acc[i].z);
            acc[i].w = fmaf(a.z, w2.w, acc[i].w);
            acc[i].x = fmaf(a.w, w3.x, acc[i].x);
            acc[i].y = fmaf(a.w, w3.y, acc[i].y);
            acc[i].z = fmaf(a.w, w3.z, acc[i].z);
            acc[i].w = fmaf(a.w, w3.w, acc[i].w);
        }
    }

    float4 bv = ((const float4*)bias)[tx];
    float csum[4] = {0.f, 0.f, 0.f, 0.f};
    float csq[4]  = {0.f, 0.f, 0.f, 0.f};
#pragma unroll
    for (int i = 0; i < 8; i++) {
        int n = n0 + ty * 8 + i;
        float4 h;
        h.x = acc[i].x + bv.x;
        h.y = acc[i].y + bv.y;
        h.z = acc[i].z + bv.z;
        h.w = acc[i].w + bv.w;
        if (n < NN) {
            ((float4*)Cout)[n * 32 + tx] = h;
            if (do_stats) {
                csum[0] += h.x; csq[0] += h.x * h.x;
                csum[1] += h.y; csq[1] += h.y * h.y;
                csum[2] += h.z; csq[2] += h.z * h.z;
                csum[3] += h.w; csq[3] += h.w * h.w;
            }
        }
    }

    if (do_stats) {
        __syncthreads();            // A-tile region no longer needed; reuse for stats
        float* ssum = As;           // [8][128]
        float* ssq  = As + 1024;    // [8][128]
#pragma unroll
        for (int j = 0; j < 4; j++) {
            ssum[ty * 128 + tx * 4 + j] = csum[j];
            ssq [ty * 128 + tx * 4 + j] = csq[j];
        }
        __syncthreads();
        if (tid < 128) {
            float s = 0.f, q = 0.f;
#pragma unroll
            for (int t = 0; t < 8; t++) {
                s += ssum[t * 128 + tid];
                q += ssq [t * 128 + tid];
            }
            atomicAdd(&g_stats[tid], s);
            atomicAdd(&g_stats[128 + tid], q);
        }
    }
}

// ---------------- BatchNorm (batch stats) + ReLU, in place ----------------
__global__ void k_bn_relu(float* __restrict__ h,
                          const float* __restrict__ gamma,
                          const float* __restrict__ beta)
{
    int idx = blockIdx.x * blockDim.x + threadIdx.x;   // over NN*32 float4s
    if (idx >= NN * 32) return;
    int c4 = idx & 31;
    float4 v  = ((float4*)h)[idx];
    float4 su = ((const float4*)g_stats)[c4];
    float4 sq = ((const float4*)g_stats)[32 + c4];
    float4 gm = ((const float4*)gamma)[c4];
    float4 bt = ((const float4*)beta)[c4];
    const float invn = 1.0f / (float)NN;
    float m, var, r;

    m = su.x * invn; var = sq.x * invn - m * m; r = rsqrtf(var + EPSV);
    v.x = fmaxf(gm.x * (v.x - m) * r + bt.x, 0.f);
    m = su.y * invn; var = sq.y * invn - m * m; r = rsqrtf(var + EPSV);
    v.y = fmaxf(gm.y * (v.y - m) * r + bt.y, 0.f);
    m = su.z * invn; var = sq.z * invn - m * m; r = rsqrtf(var + EPSV);
    v.z = fmaxf(gm.z * (v.z - m) * r + bt.z, 0.f);
    m = su.w * invn; var = sq.w * invn - m * m; r = rsqrtf(var + EPSV);
    v.w = fmaxf(gm.w * (v.w - m) * r + bt.w, 0.f);

    ((float4*)h)[idx] = v;
}

// ---------------- transpose [8][N][128] -> [N][128][8] with coalesced 32B writes ----------------
__global__ void k_interleave(float* __restrict__ out) {
    int idx = blockIdx.x * blockDim.x + threadIdx.x;   // over NN*DD
    if (idx >= NN * DD) return;
    float v[8];
#pragma unroll
    for (int e = 0; e < 8; e++) v[e] = g_out_tmp[(size_t)e * (NN * DD) + idx];
    float4* o = (float4*)out + (size_t)idx * 2;
    o[0] = make_float4(v[0], v[1], v[2], v[3]);
    o[1] = make_float4(v[4], v[5], v[6], v[7]);
}

// ---------------- launch ----------------
extern "C" void kernel_launch(void* const* d_in, const int* in_sizes, int n_in,
                              void* d_out, int out_size)
{
    const float* x      = (const float*)d_in[0];
    const int*   ei32   = (const int*)d_in[1];    // int32 or int64 (auto-detected)
    const float* W_self = (const float*)d_in[2];
    const float* W_nbr  = (const float*)d_in[3];
    const float* bprm   = (const float*)d_in[4];
    const float* gamma  = (const float*)d_in[5];
    const float* beta   = (const float*)d_in[6];
    float*       out    = (float*)d_out;

    cudaFuncSetAttribute(k_gemm, cudaFuncAttributeMaxDynamicSharedMemorySize, GEMM_SMEM);

    float *agg0, *agg1, *h, *otmp;
    cudaGetSymbolAddress((void**)&agg0, g_agg0);
    cudaGetSymbolAddress((void**)&agg1, g_agg1);
    cudaGetSymbolAddress((void**)&h,    g_h);
    cudaGetSymbolAddress((void**)&otmp, g_out_tmp);

    // CSR build
    k_detect<<<1, 32>>>(ei32);
    k_zero_deg<<<(NN + 255) / 256, 256>>>();
    k_count<<<EE / 256, 256>>>(ei32);
    k_scan1<<<SCAN_NBLK, 1024>>>();
    k_scan2<<<1, 32>>>();
    k_scan3<<<(NN + 255) / 256, 256>>>();
    k_fill<<<EE / 256, 256>>>(ei32);

    // expert-independent layer-0 aggregation
    k_aggregate<<<(NN * 32) / 256, 256>>>(x, agg0);

    const int NB_GEMM = (NN + 63) / 64;   // 1563
    for (int e = 0; e < NEXP; e++) {
        const float* Ws0 = W_self + (size_t)(e * 2 + 0) * DD * DD;
        const float* Wn0 = W_nbr  + (size_t)(e * 2 + 0) * DD * DD;
        const float* Ws1 = W_self + (size_t)(e * 2 + 1) * DD * DD;
        const float* Wn1 = W_nbr  + (size_t)(e * 2 + 1) * DD * DD;
        const float* b0  = bprm + (size_t)(e * 2 + 0) * DD;
        const float* b1  = bprm + (size_t)(e * 2 + 1) * DD;

        k_zero_stats<<<1, 256>>>();
        k_gemm<<<NB_GEMM, 256, GEMM_SMEM>>>(x, agg0, Ws0, Wn0, b0, h, 1);
        k_bn_relu<<<(NN * 32) / 256, 256>>>(h, gamma + (size_t)e * DD, beta + (size_t)e * DD);
        k_aggregate<<<(NN * 32) / 256, 256>>>(h, agg1);
        k_gemm<<<NB_GEMM, 256, GEMM_SMEM>>>(h, agg1, Ws1, Wn1, b1,
                                            otmp + (size_t)e * NN * DD, 0);
    }

    k_interleave<<<(NN * DD) / 256, 256>>>(out);
}

// round 4
// speedup vs baseline: 1.5617x; 1.5617x over previous
#include <cuda_runtime.h>
#include <cuda_bf16.h>
#include <cstdint>

#define NN 100000
#define EE 1600000
#define DD 128
#define NEXP 8
#define SCAN_NBLK 98
#define EPSV 1e-5f

// ================= scratch (static device globals) =================
__device__ int   g_deg[NN];
__device__ int   g_off[NN];
__device__ int   g_cur[NN];
__device__ float g_inv_deg[NN];
__device__ int   g_srcs[EE];
__device__ int   g_bsum[SCAN_NBLK];
__device__ int   g_is64;
__device__ float g_agg0[NN * DD];
__device__ float g_agg1[NN * DD];
__device__ float g_h[NN * DD];
__device__ float g_stats[2 * DD];
__device__ char  g_wt_hi[16][65536];   // per (e,l): 2 chunks x [128n][128k] bf16, swizzled
__device__ char  g_wt_lo[16][65536];
__device__ float g_out_tmp[(size_t)NEXP * NN * DD];

// ================= mma helpers (arch-portable: HMMA via mma.sync) =================
__device__ __forceinline__ uint32_t smem_u32(const void* p) {
    uint32_t a;
    asm("{ .reg .u64 t; cvta.to.shared.u64 t, %1; cvt.u32.u64 %0, t; }" : "=r"(a) : "l"(p));
    return a;
}
__device__ __forceinline__ void ldsm4(uint32_t* r, uint32_t addr) {
    asm volatile("ldmatrix.sync.aligned.m8n8.x4.shared.b16 {%0,%1,%2,%3}, [%4];"
        : "=r"(r[0]), "=r"(r[1]), "=r"(r[2]), "=r"(r[3]) : "r"(addr));
}
__device__ __forceinline__ void mma16816(float* d, const uint32_t* a, const uint32_t* b) {
    asm volatile("mma.sync.aligned.m16n8k16.row.col.f32.bf16.bf16.f32 "
        "{%0,%1,%2,%3}, {%4,%5,%6,%7}, {%8,%9}, {%0,%1,%2,%3};"
        : "+f"(d[0]), "+f"(d[1]), "+f"(d[2]), "+f"(d[3])
        : "r"(a[0]), "r"(a[1]), "r"(a[2]), "r"(a[3]), "r"(b[0]), "r"(b[1]));
}
// row-major [row][128 bf16] tile, 256B rows, 16B-group XOR swizzle (ldmatrix conflict-free)
__device__ __forceinline__ int swz(int row, int kbyte) {
    return row * 256 + ((((kbyte >> 4) ^ (row & 7)) << 4) | (kbyte & 15));
}

// ================= CSR build =================
__global__ void k_detect(const int* __restrict__ ei32) {
    if (threadIdx.x == 0) {
        int hz = 1;
        for (int i = 0; i < 64; i++)
            if (ei32[2 * i + 1] != 0) { hz = 0; break; }
        g_is64 = hz;
    }
}
__global__ void k_zero_deg() {
    int i = blockIdx.x * blockDim.x + threadIdx.x;
    if (i < NN) g_deg[i] = 0;
}
__global__ void k_zero_stats() {
    int i = threadIdx.x;
    if (i < 2 * DD) g_stats[i] = 0.0f;
}
__global__ void k_count(const int* __restrict__ ei32) {
    int i = blockIdx.x * blockDim.x + threadIdx.x;
    if (i < EE) {
        int d = g_is64 ? ei32[2 * (EE + i)] : ei32[EE + i];
        if ((unsigned)d < NN) atomicAdd(&g_deg[d], 1);
    }
}
__global__ void k_scan1() {
    __shared__ int s[1024];
    int t = threadIdx.x;
    int i = blockIdx.x * 1024 + t;
    int v = (i < NN) ? g_deg[i] : 0;
    s[t] = v;
    __syncthreads();
    for (int d = 1; d < 1024; d <<= 1) {
        int add = (t >= d) ? s[t - d] : 0;
        __syncthreads();
        s[t] += add;
        __syncthreads();
    }
    if (i < NN) g_off[i] = s[t] - v;
    if (t == 1023) g_bsum[blockIdx.x] = s[1023];
}
__global__ void k_scan2() {
    if (threadIdx.x == 0) {
        int run = 0;
        for (int i = 0; i < SCAN_NBLK; i++) { int v = g_bsum[i]; g_bsum[i] = run; run += v; }
    }
}
__global__ void k_scan3() {
    int i = blockIdx.x * blockDim.x + threadIdx.x;
    if (i >= NN) return;
    int off = g_off[i] + g_bsum[i >> 10];
    g_off[i] = off;
    g_cur[i] = off;
    int dg = g_deg[i];
    g_inv_deg[i] = 1.0f / (float)(dg > 0 ? dg : 1);
}
__global__ void k_fill(const int* __restrict__ ei32) {
    int i = blockIdx.x * blockDim.x + threadIdx.x;
    if (i < EE) {
        int is64 = g_is64;
        int d = is64 ? ei32[2 * (EE + i)] : ei32[EE + i];
        int s = is64 ? ei32[2 * i]        : ei32[i];
        if ((unsigned)d < NN && (unsigned)s < NN) {
            int pos = atomicAdd(&g_cur[d], 1);
            g_srcs[pos] = s;
        }
    }
}

// ================= mean aggregation =================
__global__ void k_aggregate(const float* __restrict__ feat, float* __restrict__ out) {
    int gw = (blockIdx.x * blockDim.x + threadIdx.x) >> 5;
    int lane = threadIdx.x & 31;
    if (gw >= NN) return;
    int start = g_off[gw];
    int cnt   = g_cur[gw] - start;
    const float4* f4 = (const float4*)feat;
    float4 acc = make_float4(0.f, 0.f, 0.f, 0.f);
    int j = 0;
    for (; j + 4 <= cnt; j += 4) {
        int s0 = g_srcs[start + j + 0];
        int s1 = g_srcs[start + j + 1];
        int s2 = g_srcs[start + j + 2];
        int s3 = g_srcs[start + j + 3];
        float4 v0 = f4[s0 * 32 + lane];
        float4 v1 = f4[s1 * 32 + lane];
        float4 v2 = f4[s2 * 32 + lane];
        float4 v3 = f4[s3 * 32 + lane];
        acc.x += (v0.x + v1.x) + (v2.x + v3.x);
        acc.y += (v0.y + v1.y) + (v2.y + v3.y);
        acc.z += (v0.z + v1.z) + (v2.z + v3.z);
        acc.w += (v0.w + v1.w) + (v2.w + v3.w);
    }
    for (; j < cnt; j++) {
        int s = g_srcs[start + j];
        float4 v = f4[s * 32 + lane];
        acc.x += v.x; acc.y += v.y; acc.z += v.z; acc.w += v.w;
    }
    float sc = g_inv_deg[gw];
    ((float4*)out)[gw * 32 + lane] =
        make_float4(acc.x * sc, acc.y * sc, acc.z * sc, acc.w * sc);
}

// ================= weight prep: fuse [Wself;Wnbr], transpose, bf16-split, swizzle =================
// output per inst: chunk c (k 128c..128c+127): [128 n][128 k] bf16, row 256B, XOR swizzle
__global__ void k_prep_w(const float* __restrict__ Wself, const float* __restrict__ Wnbr) {
    int inst = blockIdx.x;          // e*2 + l
    const float* ws = Wself + (size_t)inst * DD * DD;
    const float* wn = Wnbr  + (size_t)inst * DD * DD;
    char* dh = g_wt_hi[inst];
    char* dl = g_wt_lo[inst];
    for (int idx = threadIdx.x; idx < 256 * 128; idx += blockDim.x) {
        int n = idx & 127;
        int k = idx >> 7;           // 0..255
        float w = (k < 128) ? ws[k * 128 + n] : wn[(k - 128) * 128 + n];
        __nv_bfloat16 hi = __float2bfloat16(w);
        __nv_bfloat16 lo = __float2bfloat16(w - __bfloat162float(hi));
        int chunk = k >> 7;
        int kk = k & 127;
        int off = chunk * 32768 + swz(n, kk * 2);
        *(__nv_bfloat16*)(dh + off) = hi;
        *(__nv_bfloat16*)(dl + off) = lo;
    }
}

// ================= tensor-core GEMM (mma.sync): C[128,128] = [self|agg] @ Wt + bias =================
#define SM_BIAS 0
#define SM_A_HI 1024
#define SM_A_LO (1024 + 32768)
#define SM_B_HI (1024 + 65536)
#define SM_B_LO (1024 + 98304)
#define SM_TOTAL (1024 + 131072)

__device__ __forceinline__ void convert_A(char* sm, const float* __restrict__ src,
                                          int n0, int tid) {
    for (int idx = tid; idx < 4096; idx += 256) {
        int r  = idx >> 5;        // row 0..127
        int kg = idx & 31;        // float4 group -> k = kg*4, 8 bytes bf16
        int n  = n0 + r;
        float4 v = make_float4(0.f, 0.f, 0.f, 0.f);
        if (n < NN) v = ((const float4*)src)[n * 32 + kg];
        int off = swz(r, kg * 8);
        __nv_bfloat16 hx = __float2bfloat16(v.x);
        __nv_bfloat16 hy = __float2bfloat16(v.y);
        __nv_bfloat16 hz = __float2bfloat16(v.z);
        __nv_bfloat16 hw = __float2bfloat16(v.w);
        __nv_bfloat16 lx = __float2bfloat16(v.x - __bfloat162float(hx));
        __nv_bfloat16 ly = __float2bfloat16(v.y - __bfloat162float(hy));
        __nv_bfloat16 lz = __float2bfloat16(v.z - __bfloat162float(hz));
        __nv_bfloat16 lw = __float2bfloat16(v.w - __bfloat162float(hw));
        uint2 ph, pl;
        ph.x = ((uint32_t)__bfloat16_as_ushort(hy) << 16) | __bfloat16_as_ushort(hx);
        ph.y = ((uint32_t)__bfloat16_as_ushort(hw) << 16) | __bfloat16_as_ushort(hz);
        pl.x = ((uint32_t)__bfloat16_as_ushort(ly) << 16) | __bfloat16_as_ushort(lx);
        pl.y = ((uint32_t)__bfloat16_as_ushort(lw) << 16) | __bfloat16_as_ushort(lz);
        *(uint2*)(sm + SM_A_HI + off) = ph;
        *(uint2*)(sm + SM_A_LO + off) = pl;
    }
}

__global__ void __launch_bounds__(256, 1)
k_gemm_tc(const float* __restrict__ self, const float* __restrict__ agg,
          const char* __restrict__ wt_hi, const char* __restrict__ wt_lo,
          const float* __restrict__ bias, float* __restrict__ Cout)
{
    extern __shared__ char sm[];
    uint32_t smb = smem_u32(sm);
    int tid = threadIdx.x, wid = tid >> 5, lane = tid & 31;
    int n0 = blockIdx.x * 128;
    int wr = wid & 3;           // warp row tile (32 rows)
    int wc = wid >> 2;          // warp col tile (64 cols)

    if (tid < 128) ((float*)(sm + SM_BIAS))[tid] = bias[tid];

    float acc[2][8][4];
#pragma unroll
    for (int a = 0; a < 2; a++)
#pragma unroll
        for (int b = 0; b < 8; b++)
#pragma unroll
            for (int c = 0; c < 4; c++) acc[a][b][c] = 0.f;

    // lane-constant ldmatrix address components
    int lrowA = lane & 15;
    int lkgA  = lane >> 4;                         // 0/1 (k +0 / +8)
    int lnB   = (lane & 7) + ((lane >> 4) << 3);   // 0..15 within 16-n group
    int lkgB  = (lane >> 3) & 1;

#pragma unroll
    for (int chunk = 0; chunk < 2; chunk++) {
        // stage B chunk (linear copy of pre-swizzled weights)
        {
            const uint4* s0 = (const uint4*)(wt_hi + chunk * 32768);
            const uint4* s1 = (const uint4*)(wt_lo + chunk * 32768);
            uint4* d0 = (uint4*)(sm + SM_B_HI);
            uint4* d1 = (uint4*)(sm + SM_B_LO);
            for (int i = tid; i < 2048; i += 256) { d0[i] = s0[i]; d1[i] = s1[i]; }
        }
        // stage A chunk (fp32 -> bf16 hi/lo, swizzled)
        convert_A(sm, chunk == 0 ? self : agg, n0, tid);
        __syncthreads();

#pragma unroll
        for (int ks = 0; ks < 8; ks++) {
            uint32_t ah[2][4], al[2][4], bh[4][4], bl[4][4];
#pragma unroll
            for (int at = 0; at < 2; at++) {
                int row = wr * 32 + at * 16 + lrowA;
                int kb  = (ks * 2 + lkgA) * 16;
                uint32_t off = (uint32_t)swz(row, kb);
                ldsm4(ah[at], smb + SM_A_HI + off);
                ldsm4(al[at], smb + SM_A_LO + off);
            }
#pragma unroll
            for (int bp = 0; bp < 4; bp++) {
                int nrow = wc * 64 + bp * 16 + lnB;
                int kb   = (ks * 2 + lkgB) * 16;
                uint32_t off = (uint32_t)swz(nrow, kb);
                ldsm4(bh[bp], smb + SM_B_HI + off);
                ldsm4(bl[bp], smb + SM_B_LO + off);
            }
#pragma unroll
            for (int at = 0; at < 2; at++)
#pragma unroll
                for (int bp = 0; bp < 4; bp++)
#pragma unroll
                    for (int hf = 0; hf < 2; hf++) {
                        float* d = acc[at][bp * 2 + hf];
                        mma16816(d, ah[at], &bh[bp][hf * 2]);   // hi*hi
                        mma16816(d, ah[at], &bl[bp][hf * 2]);   // hi*lo
                        mma16816(d, al[at], &bh[bp][hf * 2]);   // lo*hi
                    }
        }
        __syncthreads();
    }

    // epilogue: add bias, store float2 pairs
    const float* sb = (const float*)(sm + SM_BIAS);
    int trow = lane >> 2, tc2 = lane & 3;
#pragma unroll
    for (int at = 0; at < 2; at++) {
#pragma unroll
        for (int bt = 0; bt < 8; bt++) {
            int col = wc * 64 + bt * 8 + tc2 * 2;
            float bx = sb[col], by = sb[col + 1];
            int r0 = n0 + wr * 32 + at * 16 + trow;
            float2* o = (float2*)Cout;
            if (r0 < NN)
                o[r0 * 64 + (col >> 1)] =
                    make_float2(acc[at][bt][0] + bx, acc[at][bt][1] + by);
            int r1 = r0 + 8;
            if (r1 < NN)
                o[r1 * 64 + (col >> 1)] =
                    make_float2(acc[at][bt][2] + bx, acc[at][bt][3] + by);
        }
    }
}

// ================= BN stats + BN/ReLU =================
__global__ void k_stats(const float* __restrict__ h) {
    __shared__ float ssum[8 * 128];
    __shared__ float ssq[8 * 128];
    int tid = threadIdx.x;
    int cg = tid & 31, rg = tid >> 5;
    float s[4] = {0.f, 0.f, 0.f, 0.f}, q[4] = {0.f, 0.f, 0.f, 0.f};
    for (int r = blockIdx.x * 8 + rg; r < NN; r += gridDim.x * 8) {
        float4 v = ((const float4*)h)[r * 32 + cg];
        s[0] += v.x; q[0] += v.x * v.x;
        s[1] += v.y; q[1] += v.y * v.y;
        s[2] += v.z; q[2] += v.z * v.z;
        s[3] += v.w; q[3] += v.w * v.w;
    }
#pragma unroll
    for (int j = 0; j < 4; j++) {
        ssum[rg * 128 + cg * 4 + j] = s[j];
        ssq [rg * 128 + cg * 4 + j] = q[j];
    }
    __syncthreads();
    if (tid < 128) {
        float a = 0.f, b = 0.f;
#pragma unroll
        for (int t = 0; t < 8; t++) { a += ssum[t * 128 + tid]; b += ssq[t * 128 + tid]; }
        atomicAdd(&g_stats[tid], a);
        atomicAdd(&g_stats[128 + tid], b);
    }
}

__global__ void k_bn_relu(float* __restrict__ h,
                          const float* __restrict__ gamma,
                          const float* __restrict__ beta)
{
    int idx = blockIdx.x * blockDim.x + threadIdx.x;
    if (idx >= NN * 32) return;
    int c4 = idx & 31;
    float4 v  = ((float4*)h)[idx];
    float4 su = ((const float4*)g_stats)[c4];
    float4 sq = ((const float4*)g_stats)[32 + c4];
    float4 gm = ((const float4*)gamma)[c4];
    float4 bt = ((const float4*)beta)[c4];
    const float invn = 1.0f / (float)NN;
    float m, var, r;
    m = su.x * invn; var = sq.x * invn - m * m; r = rsqrtf(var + EPSV);
    v.x = fmaxf(gm.x * (v.x - m) * r + bt.x, 0.f);
    m = su.y * invn; var = sq.y * invn - m * m; r = rsqrtf(var + EPSV);
    v.y = fmaxf(gm.y * (v.y - m) * r + bt.y, 0.f);
    m = su.z * invn; var = sq.z * invn - m * m; r = rsqrtf(var + EPSV);
    v.z = fmaxf(gm.z * (v.z - m) * r + bt.z, 0.f);
    m = su.w * invn; var = sq.w * invn - m * m; r = rsqrtf(var + EPSV);
    v.w = fmaxf(gm.w * (v.w - m) * r + bt.w, 0.f);
    ((float4*)h)[idx] = v;
}

// ================= final interleave [8][N][128] -> [N][128][8] =================
__global__ void k_interleave(float* __restrict__ out) {
    int idx = blockIdx.x * blockDim.x + threadIdx.x;
    if (idx >= NN * DD) return;
    float v[8];
#pragma unroll
    for (int e = 0; e < 8; e++) v[e] = g_out_tmp[(size_t)e * (NN * DD) + idx];
    float4* o = (float4*)out + (size_t)idx * 2;
    o[0] = make_float4(v[0], v[1], v[2], v[3]);
    o[1] = make_float4(v[4], v[5], v[6], v[7]);
}

// ================= launch =================
extern "C" void kernel_launch(void* const* d_in, const int* in_sizes, int n_in,
                              void* d_out, int out_size)
{
    const float* x      = (const float*)d_in[0];
    const int*   ei32   = (const int*)d_in[1];
    const float* W_self = (const float*)d_in[2];
    const float* W_nbr  = (const float*)d_in[3];
    const float* bprm   = (const float*)d_in[4];
    const float* gamma  = (const float*)d_in[5];
    const float* beta   = (const float*)d_in[6];
    float*       out    = (float*)d_out;

    cudaFuncSetAttribute(k_gemm_tc, cudaFuncAttributeMaxDynamicSharedMemorySize, SM_TOTAL);

    float *agg0, *agg1, *h, *otmp;
    char *wth, *wtl;
    cudaGetSymbolAddress((void**)&agg0, g_agg0);
    cudaGetSymbolAddress((void**)&agg1, g_agg1);
    cudaGetSymbolAddress((void**)&h,    g_h);
    cudaGetSymbolAddress((void**)&otmp, g_out_tmp);
    cudaGetSymbolAddress((void**)&wth,  g_wt_hi);
    cudaGetSymbolAddress((void**)&wtl,  g_wt_lo);

    // CSR build
    k_detect<<<1, 32>>>(ei32);
    k_zero_deg<<<(NN + 255) / 256, 256>>>();
    k_count<<<EE / 256, 256>>>(ei32);
    k_scan1<<<SCAN_NBLK, 1024>>>();
    k_scan2<<<1, 32>>>();
    k_scan3<<<(NN + 255) / 256, 256>>>();
    k_fill<<<EE / 256, 256>>>(ei32);

    // weight prep + expert-independent layer-0 aggregation
    k_prep_w<<<16, 256>>>(W_self, W_nbr);
    k_aggregate<<<(NN * 32) / 256, 256>>>(x, agg0);

    const int NB = (NN + 127) / 128;   // 782
    for (int e = 0; e < NEXP; e++) {
        int i0 = e * 2, i1 = e * 2 + 1;
        const float* b0 = bprm + (size_t)i0 * DD;
        const float* b1 = bprm + (size_t)i1 * DD;

        k_gemm_tc<<<NB, 256, SM_TOTAL>>>(x, agg0, (const char*)(wth + (size_t)i0 * 65536),
                                         (const char*)(wtl + (size_t)i0 * 65536), b0, h);
        k_zero_stats<<<1, 256>>>();
        k_stats<<<512, 256>>>(h);
        k_bn_relu<<<(NN * 32) / 256, 256>>>(h, gamma + (size_t)e * DD, beta + (size_t)e * DD);
        k_aggregate<<<(NN * 32) / 256, 256>>>(h, agg1);
        k_gemm_tc<<<NB, 256, SM_TOTAL>>>(h, agg1, (const char*)(wth + (size_t)i1 * 65536),
                                         (const char*)(wtl + (size_t)i1 * 65536), b1,
                                         otmp + (size_t)e * NN * DD);
    }

    k_interleave<<<(NN * DD) / 256, 256>>>(out);
}

// round 5
// speedup vs baseline: 2.3555x; 1.5083x over previous
#include <cuda_runtime.h>
#include <cuda_bf16.h>
#include <cstdint>

#define NN 100000
#define EE 1600000
#define DD 128
#define NEXP 8
#define SCAN_NBLK 98
#define EPSV 1e-5f

// ================= scratch (static device globals) =================
__device__ int   g_deg[NN];
__device__ int   g_off[NN];
__device__ int   g_cur[NN];
__device__ float g_inv_deg[NN];
__device__ int   g_srcs[EE];
__device__ int   g_bsum[SCAN_NBLK];
__device__ int   g_is64;
__device__ float g_agg0[NN * DD];
__device__ float g_agg1[NN * DD];
__device__ float g_stats_s[NEXP * DD];   // per-expert column sums
__device__ float g_stats_q[NEXP * DD];   // per-expert column sumsq
__device__ float g_scale[NEXP * DD];
__device__ float g_shift[NEXP * DD];
__device__ char  g_wt_hi[16][65536];     // per (e,l): 2 chunks x [128n][128k] bf16, swizzled
__device__ char  g_wt_lo[16][65536];
__device__ float g_h_all[(size_t)NEXP * NN * DD];     // pre-BN layer-0 outputs
__device__ float g_out_tmp[(size_t)NEXP * NN * DD];   // layer-1 outputs [8][N][128]

// ================= mma helpers =================
__device__ __forceinline__ uint32_t smem_u32(const void* p) {
    uint32_t a;
    asm("{ .reg .u64 t; cvta.to.shared.u64 t, %1; cvt.u32.u64 %0, t; }" : "=r"(a) : "l"(p));
    return a;
}
__device__ __forceinline__ void ldsm4(uint32_t* r, uint32_t addr) {
    asm volatile("ldmatrix.sync.aligned.m8n8.x4.shared.b16 {%0,%1,%2,%3}, [%4];"
        : "=r"(r[0]), "=r"(r[1]), "=r"(r[2]), "=r"(r[3]) : "r"(addr));
}
__device__ __forceinline__ void mma16816(float* d, const uint32_t* a, const uint32_t* b) {
    asm volatile("mma.sync.aligned.m16n8k16.row.col.f32.bf16.bf16.f32 "
        "{%0,%1,%2,%3}, {%4,%5,%6,%7}, {%8,%9}, {%0,%1,%2,%3};"
        : "+f"(d[0]), "+f"(d[1]), "+f"(d[2]), "+f"(d[3])
        : "r"(a[0]), "r"(a[1]), "r"(a[2]), "r"(a[3]), "r"(b[0]), "r"(b[1]));
}
// row-major [row][128 bf16] tile, 256B rows, 16B-group XOR swizzle
__device__ __forceinline__ int swz(int row, int kbyte) {
    return row * 256 + ((((kbyte >> 4) ^ (row & 7)) << 4) | (kbyte & 15));
}

// ================= CSR build =================
__global__ void k_detect(const int* __restrict__ ei32) {
    if (threadIdx.x == 0) {
        int hz = 1;
        for (int i = 0; i < 64; i++)
            if (ei32[2 * i + 1] != 0) { hz = 0; break; }
        g_is64 = hz;
    }
}
__global__ void k_zero_deg() {
    int i = blockIdx.x * blockDim.x + threadIdx.x;
    if (i < NN) g_deg[i] = 0;
}
__global__ void k_zero_stats8() {
    int i = blockIdx.x * blockDim.x + threadIdx.x;
    if (i < NEXP * DD) { g_stats_s[i] = 0.f; g_stats_q[i] = 0.f; }
}
__global__ void k_count(const int* __restrict__ ei32) {
    int i = blockIdx.x * blockDim.x + threadIdx.x;
    if (i < EE) {
        int d = g_is64 ? ei32[2 * (EE + i)] : ei32[EE + i];
        if ((unsigned)d < NN) atomicAdd(&g_deg[d], 1);
    }
}
__global__ void k_scan1() {
    __shared__ int s[1024];
    int t = threadIdx.x;
    int i = blockIdx.x * 1024 + t;
    int v = (i < NN) ? g_deg[i] : 0;
    s[t] = v;
    __syncthreads();
    for (int d = 1; d < 1024; d <<= 1) {
        int add = (t >= d) ? s[t - d] : 0;
        __syncthreads();
        s[t] += add;
        __syncthreads();
    }
    if (i < NN) g_off[i] = s[t] - v;
    if (t == 1023) g_bsum[blockIdx.x] = s[1023];
}
__global__ void k_scan2() {
    if (threadIdx.x == 0) {
        int run = 0;
        for (int i = 0; i < SCAN_NBLK; i++) { int v = g_bsum[i]; g_bsum[i] = run; run += v; }
    }
}
__global__ void k_scan3() {
    int i = blockIdx.x * blockDim.x + threadIdx.x;
    if (i >= NN) return;
    int off = g_off[i] + g_bsum[i >> 10];
    g_off[i] = off;
    g_cur[i] = off;
    int dg = g_deg[i];
    g_inv_deg[i] = 1.0f / (float)(dg > 0 ? dg : 1);
}
__global__ void k_fill(const int* __restrict__ ei32) {
    int i = blockIdx.x * blockDim.x + threadIdx.x;
    if (i < EE) {
        int is64 = g_is64;
        int d = is64 ? ei32[2 * (EE + i)] : ei32[EE + i];
        int s = is64 ? ei32[2 * i]        : ei32[i];
        if ((unsigned)d < NN && (unsigned)s < NN) {
            int pos = atomicAdd(&g_cur[d], 1);
            g_srcs[pos] = s;
        }
    }
}

// ================= mean aggregation (optionally fused BN+ReLU on gathered values) =================
template <bool BN>
__global__ void k_agg(const float* __restrict__ feat, float* __restrict__ out,
                      const float* __restrict__ scale, const float* __restrict__ shift)
{
    int gw = (blockIdx.x * blockDim.x + threadIdx.x) >> 5;
    int lane = threadIdx.x & 31;
    if (gw >= NN) return;
    int start = g_off[gw];
    int cnt   = g_cur[gw] - start;
    const float4* f4 = (const float4*)feat;
    float4 sc4, sh4;
    if (BN) { sc4 = ((const float4*)scale)[lane]; sh4 = ((const float4*)shift)[lane]; }
    float4 acc = make_float4(0.f, 0.f, 0.f, 0.f);
    int j = 0;

#define GATHER_BLK(U) \
    { \
        int s[U]; \
        _Pragma("unroll") for (int u = 0; u < U; u++) s[u] = g_srcs[start + j + u]; \
        float4 v[U]; \
        _Pragma("unroll") for (int u = 0; u < U; u++) v[u] = f4[s[u] * 32 + lane]; \
        _Pragma("unroll") for (int u = 0; u < U; u++) { \
            float4 t = v[u]; \
            if (BN) { \
                t.x = fmaxf(fmaf(t.x, sc4.x, sh4.x), 0.f); \
                t.y = fmaxf(fmaf(t.y, sc4.y, sh4.y), 0.f); \
                t.z = fmaxf(fmaf(t.z, sc4.z, sh4.z), 0.f); \
                t.w = fmaxf(fmaf(t.w, sc4.w, sh4.w), 0.f); \
            } \
            acc.x += t.x; acc.y += t.y; acc.z += t.z; acc.w += t.w; \
        } \
        j += U; \
    }

    for (; j + 8 <= cnt;) GATHER_BLK(8)
    if (j + 4 <= cnt) GATHER_BLK(4)
    if (j + 2 <= cnt) GATHER_BLK(2)
    if (j + 1 <= cnt) GATHER_BLK(1)
#undef GATHER_BLK

    float sc = g_inv_deg[gw];
    ((float4*)out)[gw * 32 + lane] =
        make_float4(acc.x * sc, acc.y * sc, acc.z * sc, acc.w * sc);
}

// ================= weight prep: fuse [Wself;Wnbr], transpose, bf16-split, swizzle =================
__global__ void k_prep_w(const float* __restrict__ Wself, const float* __restrict__ Wnbr) {
    int inst = blockIdx.x;          // e*2 + l
    const float* ws = Wself + (size_t)inst * DD * DD;
    const float* wn = Wnbr  + (size_t)inst * DD * DD;
    char* dh = g_wt_hi[inst];
    char* dl = g_wt_lo[inst];
    for (int idx = threadIdx.x; idx < 256 * 128; idx += blockDim.x) {
        int n = idx & 127;
        int k = idx >> 7;
        float w = (k < 128) ? ws[k * 128 + n] : wn[(k - 128) * 128 + n];
        __nv_bfloat16 hi = __float2bfloat16(w);
        __nv_bfloat16 lo = __float2bfloat16(w - __bfloat162float(hi));
        int chunk = k >> 7;
        int kk = k & 127;
        int off = chunk * 32768 + swz(n, kk * 2);
        *(__nv_bfloat16*)(dh + off) = hi;
        *(__nv_bfloat16*)(dl + off) = lo;
    }
}

// ================= A-tile conversion (fp32 -> bf16 hi/lo, swizzled), optional BN+ReLU =================
template <bool BN>
__device__ __forceinline__ void convert_A(char* sm, int base, const float* __restrict__ src,
                                          const float* __restrict__ scale,
                                          const float* __restrict__ shift,
                                          int n0, int tid)
{
    for (int idx = tid; idx < 4096; idx += 256) {
        int r  = idx >> 5;
        int kg = idx & 31;
        int n  = n0 + r;
        float4 v = make_float4(0.f, 0.f, 0.f, 0.f);
        if (n < NN) v = ((const float4*)src)[n * 32 + kg];
        if (BN) {
            float4 sc = ((const float4*)scale)[kg];
            float4 sh = ((const float4*)shift)[kg];
            v.x = fmaxf(fmaf(v.x, sc.x, sh.x), 0.f);
            v.y = fmaxf(fmaf(v.y, sc.y, sh.y), 0.f);
            v.z = fmaxf(fmaf(v.z, sc.z, sh.z), 0.f);
            v.w = fmaxf(fmaf(v.w, sc.w, sh.w), 0.f);
        }
        int off = swz(r, kg * 8);
        __nv_bfloat16 hx = __float2bfloat16(v.x);
        __nv_bfloat16 hy = __float2bfloat16(v.y);
        __nv_bfloat16 hz = __float2bfloat16(v.z);
        __nv_bfloat16 hw = __float2bfloat16(v.w);
        __nv_bfloat16 lx = __float2bfloat16(v.x - __bfloat162float(hx));
        __nv_bfloat16 ly = __float2bfloat16(v.y - __bfloat162float(hy));
        __nv_bfloat16 lz = __float2bfloat16(v.z - __bfloat162float(hz));
        __nv_bfloat16 lw = __float2bfloat16(v.w - __bfloat162float(hw));
        uint2 ph, pl;
        ph.x = ((uint32_t)__bfloat16_as_ushort(hy) << 16) | __bfloat16_as_ushort(hx);
        ph.y = ((uint32_t)__bfloat16_as_ushort(hw) << 16) | __bfloat16_as_ushort(hz);
        pl.x = ((uint32_t)__bfloat16_as_ushort(ly) << 16) | __bfloat16_as_ushort(lx);
        pl.y = ((uint32_t)__bfloat16_as_ushort(lw) << 16) | __bfloat16_as_ushort(lz);
        *(uint2*)(sm + base + off) = ph;
        *(uint2*)(sm + base + 32768 + off) = pl;
    }
}

// ================= batched layer-0 GEMM: all 8 experts, A converted once =================
// smem: A: [c0hi, c0lo, c1hi, c1lo] @0..131071 ; B: [hi, lo] @131072..196607
#define G0_B 131072
#define G0_TOTAL 196608

__global__ void __launch_bounds__(256, 1)
k_gemm0_all(const float* __restrict__ x, const float* __restrict__ agg0,
            const char* __restrict__ wth_all, const char* __restrict__ wtl_all,
            const float* __restrict__ bprm, float* __restrict__ h_all)
{
    extern __shared__ char sm[];
    uint32_t smb = smem_u32(sm);
    int tid = threadIdx.x, wid = tid >> 5, lane = tid & 31;
    int n0 = blockIdx.x * 128;
    int wr = wid & 3, wc = wid >> 2;

    convert_A<false>(sm, 0,     x,    nullptr, nullptr, n0, tid);
    convert_A<false>(sm, 65536, agg0, nullptr, nullptr, n0, tid);

    int lrowA = lane & 15;
    int lkgA  = lane >> 4;
    int lnB   = (lane & 7) + ((lane >> 4) << 3);
    int lkgB  = (lane >> 3) & 1;
    int trow = lane >> 2, tc2 = lane & 3;

    for (int e = 0; e < NEXP; e++) {
        float acc[2][8][4];
#pragma unroll
        for (int a = 0; a < 2; a++)
#pragma unroll
            for (int b = 0; b < 8; b++)
#pragma unroll
                for (int c = 0; c < 4; c++) acc[a][b][c] = 0.f;

        const char* wh = wth_all + (size_t)(e * 2) * 65536;
        const char* wl = wtl_all + (size_t)(e * 2) * 65536;

#pragma unroll
        for (int chunk = 0; chunk < 2; chunk++) {
            __syncthreads();   // previous consumers of B done / A writes visible (first iter)
            {
                const uint4* s0 = (const uint4*)(wh + chunk * 32768);
                const uint4* s1 = (const uint4*)(wl + chunk * 32768);
                uint4* d0 = (uint4*)(sm + G0_B);
                uint4* d1 = (uint4*)(sm + G0_B + 32768);
                for (int i = tid; i < 2048; i += 256) { d0[i] = s0[i]; d1[i] = s1[i]; }
            }
            __syncthreads();
            int abase = chunk * 65536;
#pragma unroll
            for (int ks = 0; ks < 8; ks++) {
                uint32_t ah[2][4], al[2][4], bh[4][4], bl[4][4];
#pragma unroll
                for (int at = 0; at < 2; at++) {
                    int row = wr * 32 + at * 16 + lrowA;
                    int kb  = (ks * 2 + lkgA) * 16;
                    uint32_t off = (uint32_t)swz(row, kb);
                    ldsm4(ah[at], smb + abase + off);
                    ldsm4(al[at], smb + abase + 32768 + off);
                }
#pragma unroll
                for (int bp = 0; bp < 4; bp++) {
                    int nrow = wc * 64 + bp * 16 + lnB;
                    int kb   = (ks * 2 + lkgB) * 16;
                    uint32_t off = (uint32_t)swz(nrow, kb);
                    ldsm4(bh[bp], smb + G0_B + off);
                    ldsm4(bl[bp], smb + G0_B + 32768 + off);
                }
#pragma unroll
                for (int at = 0; at < 2; at++)
#pragma unroll
                    for (int bp = 0; bp < 4; bp++)
#pragma unroll
                        for (int hf = 0; hf < 2; hf++) {
                            float* d = acc[at][bp * 2 + hf];
                            mma16816(d, ah[at], &bh[bp][hf * 2]);
                            mma16816(d, ah[at], &bl[bp][hf * 2]);
                            mma16816(d, al[at], &bh[bp][hf * 2]);
                        }
            }
        }

        // epilogue: bias, store h_all[e], fused column stats (shfl-reduce + global RED)
        const float* be = bprm + (size_t)(e * 2) * DD;
        float2* o = (float2*)(h_all + (size_t)e * NN * DD);
#pragma unroll
        for (int bt = 0; bt < 8; bt++) {
            int col = wc * 64 + bt * 8 + tc2 * 2;
            float bx = be[col], by = be[col + 1];
            float sx = 0.f, sy = 0.f, qx = 0.f, qy = 0.f;
#pragma unroll
            for (int at = 0; at < 2; at++) {
                int r0 = n0 + wr * 32 + at * 16 + trow;
                float v0x = acc[at][bt][0] + bx, v0y = acc[at][bt][1] + by;
                float v1x = acc[at][bt][2] + bx, v1y = acc[at][bt][3] + by;
                if (r0 < NN) {
                    o[r0 * 64 + (col >> 1)] = make_float2(v0x, v0y);
                    sx += v0x; sy += v0y; qx += v0x * v0x; qy += v0y * v0y;
                }
                if (r0 + 8 < NN) {
                    o[(r0 + 8) * 64 + (col >> 1)] = make_float2(v1x, v1y);
                    sx += v1x; sy += v1y; qx += v1x * v1x; qy += v1y * v1y;
                }
            }
#pragma unroll
            for (int off = 4; off < 32; off <<= 1) {
                sx += __shfl_xor_sync(0xFFFFFFFF, sx, off);
                sy += __shfl_xor_sync(0xFFFFFFFF, sy, off);
                qx += __shfl_xor_sync(0xFFFFFFFF, qx, off);
                qy += __shfl_xor_sync(0xFFFFFFFF, qy, off);
            }
            if (lane < 4) {
                atomicAdd(&g_stats_s[e * DD + col], sx);
                atomicAdd(&g_stats_s[e * DD + col + 1], sy);
                atomicAdd(&g_stats_q[e * DD + col], qx);
                atomicAdd(&g_stats_q[e * DD + col + 1], qy);
            }
        }
    }
}

// ================= finalize BN: scale/shift per (expert, col) =================
__global__ void k_finalize(const float* __restrict__ gamma, const float* __restrict__ beta) {
    int i = threadIdx.x + blockIdx.x * blockDim.x;   // 0..1023
    if (i >= NEXP * DD) return;
    const float invn = 1.0f / (float)NN;
    float m = g_stats_s[i] * invn;
    float var = g_stats_q[i] * invn - m * m;
    float r = rsqrtf(var + EPSV);
    float sc = gamma[i] * r;
    g_scale[i] = sc;
    g_shift[i] = beta[i] - m * sc;
}

// ================= layer-1 GEMM: C = [bn_relu(h) | agg1] @ Wt + bias =================
#define SM_BIAS 0
#define SM_A_HI 1024
#define SM_A_LO (1024 + 32768)
#define SM_B_HI (1024 + 65536)
#define SM_B_LO (1024 + 98304)
#define SM_TOTAL (1024 + 131072)

__global__ void __launch_bounds__(256, 1)
k_gemm1(const float* __restrict__ hpre, const float* __restrict__ agg1,
        const char* __restrict__ wt_hi, const char* __restrict__ wt_lo,
        const float* __restrict__ bias,
        const float* __restrict__ scale, const float* __restrict__ shift,
        float* __restrict__ Cout)
{
    extern __shared__ char sm[];
    uint32_t smb = smem_u32(sm);
    int tid = threadIdx.x, wid = tid >> 5, lane = tid & 31;
    int n0 = blockIdx.x * 128;
    int wr = wid & 3, wc = wid >> 2;

    if (tid < 128) ((float*)(sm + SM_BIAS))[tid] = bias[tid];

    float acc[2][8][4];
#pragma unroll
    for (int a = 0; a < 2; a++)
#pragma unroll
        for (int b = 0; b < 8; b++)
#pragma unroll
            for (int c = 0; c < 4; c++) acc[a][b][c] = 0.f;

    int lrowA = lane & 15;
    int lkgA  = lane >> 4;
    int lnB   = (lane & 7) + ((lane >> 4) << 3);
    int lkgB  = (lane >> 3) & 1;

#pragma unroll
    for (int chunk = 0; chunk < 2; chunk++) {
        {
            const uint4* s0 = (const uint4*)(wt_hi + chunk * 32768);
            const uint4* s1 = (const uint4*)(wt_lo + chunk * 32768);
            uint4* d0 = (uint4*)(sm + SM_B_HI);
            uint4* d1 = (uint4*)(sm + SM_B_LO);
            for (int i = tid; i < 2048; i += 256) { d0[i] = s0[i]; d1[i] = s1[i]; }
        }
        if (chunk == 0)
            convert_A<true>(sm, SM_A_HI, hpre, scale, shift, n0, tid);
        else
            convert_A<false>(sm, SM_A_HI, agg1, nullptr, nullptr, n0, tid);
        __syncthreads();

#pragma unroll
        for (int ks = 0; ks < 8; ks++) {
            uint32_t ah[2][4], al[2][4], bh[4][4], bl[4][4];
#pragma unroll
            for (int at = 0; at < 2; at++) {
                int row = wr * 32 + at * 16 + lrowA;
                int kb  = (ks * 2 + lkgA) * 16;
                uint32_t off = (uint32_t)swz(row, kb);
                ldsm4(ah[at], smb + SM_A_HI + off);
                ldsm4(al[at], smb + SM_A_LO + off);
            }
#pragma unroll
            for (int bp = 0; bp < 4; bp++) {
                int nrow = wc * 64 + bp * 16 + lnB;
                int kb   = (ks * 2 + lkgB) * 16;
                uint32_t off = (uint32_t)swz(nrow, kb);
                ldsm4(bh[bp], smb + SM_B_HI + off);
                ldsm4(bl[bp], smb + SM_B_LO + off);
            }
#pragma unroll
            for (int at = 0; at < 2; at++)
#pragma unroll
                for (int bp = 0; bp < 4; bp++)
#pragma unroll
                    for (int hf = 0; hf < 2; hf++) {
                        float* d = acc[at][bp * 2 + hf];
                        mma16816(d, ah[at], &bh[bp][hf * 2]);
                        mma16816(d, ah[at], &bl[bp][hf * 2]);
                        mma16816(d, al[at], &bh[bp][hf * 2]);
                    }
        }
        __syncthreads();
    }

    const float* sb = (const float*)(sm + SM_BIAS);
    int trow = lane >> 2, tc2 = lane & 3;
#pragma unroll
    for (int at = 0; at < 2; at++) {
#pragma unroll
        for (int bt = 0; bt < 8; bt++) {
            int col = wc * 64 + bt * 8 + tc2 * 2;
            float bx = sb[col], by = sb[col + 1];
            int r0 = n0 + wr * 32 + at * 16 + trow;
            float2* o = (float2*)Cout;
            if (r0 < NN)
                o[r0 * 64 + (col >> 1)] =
                    make_float2(acc[at][bt][0] + bx, acc[at][bt][1] + by);
            if (r0 + 8 < NN)
                o[(r0 + 8) * 64 + (col >> 1)] =
                    make_float2(acc[at][bt][2] + bx, acc[at][bt][3] + by);
        }
    }
}

// ================= final interleave [8][N][128] -> [N][128][8] =================
__global__ void k_interleave(float* __restrict__ out) {
    int idx = blockIdx.x * blockDim.x + threadIdx.x;
    if (idx >= NN * DD) return;
    float v[8];
#pragma unroll
    for (int e = 0; e < 8; e++) v[e] = g_out_tmp[(size_t)e * (NN * DD) + idx];
    float4* o = (float4*)out + (size_t)idx * 2;
    o[0] = make_float4(v[0], v[1], v[2], v[3]);
    o[1] = make_float4(v[4], v[5], v[6], v[7]);
}

// ================= launch =================
extern "C" void kernel_launch(void* const* d_in, const int* in_sizes, int n_in,
                              void* d_out, int out_size)
{
    const float* x      = (const float*)d_in[0];
    const int*   ei32   = (const int*)d_in[1];
    const float* W_self = (const float*)d_in[2];
    const float* W_nbr  = (const float*)d_in[3];
    const float* bprm   = (const float*)d_in[4];
    const float* gamma  = (const float*)d_in[5];
    const float* beta   = (const float*)d_in[6];
    float*       out    = (float*)d_out;

    cudaFuncSetAttribute(k_gemm0_all, cudaFuncAttributeMaxDynamicSharedMemorySize, G0_TOTAL);
    cudaFuncSetAttribute(k_gemm1, cudaFuncAttributeMaxDynamicSharedMemorySize, SM_TOTAL);

    float *agg0, *agg1, *hall, *otmp, *scl, *shf;
    char *wth, *wtl;
    cudaGetSymbolAddress((void**)&agg0, g_agg0);
    cudaGetSymbolAddress((void**)&agg1, g_agg1);
    cudaGetSymbolAddress((void**)&hall, g_h_all);
    cudaGetSymbolAddress((void**)&otmp, g_out_tmp);
    cudaGetSymbolAddress((void**)&scl,  g_scale);
    cudaGetSymbolAddress((void**)&shf,  g_shift);
    cudaGetSymbolAddress((void**)&wth,  g_wt_hi);
    cudaGetSymbolAddress((void**)&wtl,  g_wt_lo);

    // CSR build
    k_detect<<<1, 32>>>(ei32);
    k_zero_deg<<<(NN + 255) / 256, 256>>>();
    k_zero_stats8<<<1, 1024>>>();
    k_count<<<EE / 256, 256>>>(ei32);
    k_scan1<<<SCAN_NBLK, 1024>>>();
    k_scan2<<<1, 32>>>();
    k_scan3<<<(NN + 255) / 256, 256>>>();
    k_fill<<<EE / 256, 256>>>(ei32);

    // weight prep + layer-0 aggregation (expert independent)
    k_prep_w<<<16, 256>>>(W_self, W_nbr);
    k_agg<false><<<NN / 8, 256>>>(x, agg0, nullptr, nullptr);

    const int NB = (NN + 127) / 128;   // 782

    // layer 0 for ALL experts in one launch (+ fused stats)
    k_gemm0_all<<<NB, 256, G0_TOTAL>>>(x, agg0, wth, wtl, bprm, hall);
    k_finalize<<<1, 1024>>>(gamma, beta);

    // layer 1 per expert (BN+ReLU fused into gather and A-convert)
    for (int e = 0; e < NEXP; e++) {
        int i1 = e * 2 + 1;
        const float* b1 = bprm + (size_t)i1 * DD;
        const float* he = hall + (size_t)e * NN * DD;
        k_agg<true><<<NN / 8, 256>>>(he, agg1, scl + e * DD, shf + e * DD);
        k_gemm1<<<NB, 256, SM_TOTAL>>>(he, agg1,
                                       (const char*)(wth + (size_t)i1 * 65536),
                                       (const char*)(wtl + (size_t)i1 * 65536),
                                       b1, scl + e * DD, shf + e * DD,
                                       otmp + (size_t)e * NN * DD);
    }

    k_interleave<<<(NN * DD) / 256, 256>>>(out);
}